// round 14
// baseline (speedup 1.0000x reference)
#include <cuda_runtime.h>
#include <cuda_fp16.h>
#include <math.h>

// Problem constants (fixed shapes)
#define NN 100000
#define EE 1600000
#define HH 128
#define BB 16
#define MM 2048
#define LL 3

// -------- static device scratch (no allocations allowed) --------
__device__ __half g_Abuf[2][(size_t)NN * HH];  // ping-pong h @ Wm_top (fp16)
__device__ __half g_Bbuf[2][(size_t)NN * HH];  // ping-pong h @ Wm_bot (fp16)
__device__ __half g_hh[(size_t)NN * HH];       // node hidden state (fp16)
__device__ __half g_Wth[7 * HH * HH];          // W^T hi (fp16)
__device__ __half g_Wtl[7 * HH * HH];          // W^T lo (fp16 of residual)
__device__ int    g_src[EE];
__device__ int    g_tgt[EE];
__device__ int    g_rank[EE];
__device__ int    g_col[EE];
__device__ int    g_deg[NN];
__device__ int    g_off[NN];
__device__ int    g_batchi[NN];
__device__ int    g_bsums[128];
__device__ float  g_gsum[BB * HH];
__device__ int    g_cnt[BB];
__device__ float  g_t1[BB * 2 * HH];
__device__ int    g_flags;

// ----------------------------------------------------------------
__global__ void zero_kernel() {
    int i = blockIdx.x * blockDim.x + threadIdx.x;
    if (i < NN) g_deg[i] = 0;
    if (i < BB * HH) g_gsum[i] = 0.0f;
    if (i < BB) g_cnt[i] = 0;
    if (i == 0) g_flags = 0;
}

__global__ void detect_kernel(const void* __restrict__ ep, const void* __restrict__ bp) {
    int j = threadIdx.x;
    long long pos = (long long)j * (EE / 256);
    long long v = ((const long long*)ep)[pos];
    if (v < 0 || v >= NN) atomicOr(&g_flags, 1);
    long long bpos = (long long)(NN / 4) + j;
    long long bv = ((const long long*)bp)[bpos];
    if (bv < 0 || bv >= BB) atomicOr(&g_flags, 2);
}

// weight transpose + fp16 hi/lo split
__global__ void prep_kernel(const float* __restrict__ We, const float* __restrict__ Wm) {
    int idx = blockIdx.x * blockDim.x + threadIdx.x;
    if (idx >= 7 * HH * HH) return;
    int mat = idx >> 14;
    int r = (idx >> 7) & 127;
    int c = idx & 127;
    float v;
    if (mat == 0) {
        v = We[r * HH + c];
    } else {
        int l = (mat - 1) >> 1;
        int hf = (mat - 1) & 1;
        v = Wm[((size_t)l * 2 * HH + hf * HH + r) * HH + c];
    }
    __half hi = __float2half_rn(v);
    g_Wth[mat * HH * HH + c * HH + r] = hi;
    g_Wtl[mat * HH * HH + c * HH + r] = __float2half_rn(v - __half2float(hi));
}

// convert + degree histogram with ranks + batch counts (small grid-stride)
__global__ void __launch_bounds__(256) convert_kernel(const void* __restrict__ ep,
                                                      const void* __restrict__ bp) {
    int f = g_flags;
    int stride = gridDim.x * blockDim.x;
    for (int i = blockIdx.x * blockDim.x + threadIdx.x; i < EE / 2; i += stride) {
        int s0, s1, t0, t1;
        if (f & 1) {
            int2 sv = ((const int2*)ep)[i];
            int2 tv = ((const int2*)((const int*)ep + EE))[i];
            s0 = sv.x; s1 = sv.y; t0 = tv.x; t1 = tv.y;
        } else {
            longlong2 sv = ((const longlong2*)ep)[i];
            longlong2 tv = ((const longlong2*)((const long long*)ep + EE))[i];
            s0 = (int)sv.x; s1 = (int)sv.y; t0 = (int)tv.x; t1 = (int)tv.y;
        }
        *(int2*)(g_src + 2 * i) = make_int2(s0, s1);
        *(int2*)(g_tgt + 2 * i) = make_int2(t0, t1);
        int r0 = atomicAdd(&g_deg[t0], 1);
        int r1 = atomicAdd(&g_deg[t1], 1);
        *(int2*)(g_rank + 2 * i) = make_int2(r0, r1);
    }
    for (int i = blockIdx.x * blockDim.x + threadIdx.x; i < NN; i += stride) {
        int b = (f & 2) ? ((const int*)bp)[i] : (int)((const long long*)bp)[i];
        g_batchi[i] = b;
        atomicAdd(&g_cnt[b], 1);
    }
}

__global__ void scan1_kernel() {
    __shared__ int sh[1024];
    int t = threadIdx.x;
    int i = blockIdx.x * 1024 + t;
    int v = (i < NN) ? g_deg[i] : 0;
    sh[t] = v;
    __syncthreads();
#pragma unroll
    for (int s = 1; s < 1024; s <<= 1) {
        int x = (t >= s) ? sh[t - s] : 0;
        __syncthreads();
        sh[t] += x;
        __syncthreads();
    }
    if (i < NN) g_off[i] = sh[t] - v;
    if (t == 1023) g_bsums[blockIdx.x] = sh[1023];
}

__global__ void scan2_kernel(int nb) {
    __shared__ int sh[128];
    int t = threadIdx.x;
    int v = (t < nb) ? g_bsums[t] : 0;
    sh[t] = v;
    __syncthreads();
#pragma unroll
    for (int s = 1; s < 128; s <<= 1) {
        int x = (t >= s) ? sh[t - s] : 0;
        __syncthreads();
        sh[t] += x;
        __syncthreads();
    }
    if (t < nb) g_bsums[t] = sh[t] - v;
}

__global__ void scan3_kernel() {
    int i = blockIdx.x * 1024 + threadIdx.x;
    if (i < NN) g_off[i] += g_bsums[blockIdx.x];
}

__global__ void fill_kernel() {
    int i = blockIdx.x * blockDim.x + threadIdx.x;
    if (i >= EE / 2) return;
    int2 t = *(const int2*)(g_tgt + 2 * i);
    int2 s = *(const int2*)(g_src + 2 * i);
    int2 r = *(const int2*)(g_rank + 2 * i);
    g_col[g_off[t.x] + r.x] = s.x;
    g_col[g_off[t.y] + r.y] = s.y;
}

// -------- shared GEMM helpers ----------------------------------------------
#define SASTRIDE 40

__device__ __forceinline__ unsigned smaddr(const void* p) {
    return (unsigned)__cvta_generic_to_shared(p);
}

#define LDMX4(R, addr)                                                           \
    asm volatile("ldmatrix.sync.aligned.m8n8.x4.shared.b16 {%0,%1,%2,%3}, [%4];" \
                 : "=r"((R)[0]), "=r"((R)[1]), "=r"((R)[2]), "=r"((R)[3])        \
                 : "r"(addr))

#define MMA16816(C, A, b0, b1)                                                   \
    asm volatile(                                                                \
        "mma.sync.aligned.m16n8k16.row.col.f32.f16.f16.f32 "                     \
        "{%0,%1,%2,%3}, {%4,%5,%6,%7}, {%8,%9}, {%0,%1,%2,%3};"                  \
        : "+f"((C)[0]), "+f"((C)[1]), "+f"((C)[2]), "+f"((C)[3])                 \
        : "r"((A)[0]), "r"((A)[1]), "r"((A)[2]), "r"((A)[3]), "r"(b0), "r"(b1))

#define CPA16(dst, src, sz)                                                       \
    asm volatile("cp.async.cg.shared.global [%0], [%1], 16, %2;"                  \
                 :: "r"(dst), "l"(src), "r"(sz))

#define GEMM_COMPUTE(s)                                                           \
    _Pragma("unroll") for (int ks = 0; ks < 2; ks++) {                            \
        const int kk = ks * 16;                                                   \
        unsigned ah[2][4];                                                        \
        _Pragma("unroll") for (int f = 0; f < 2; f++) {                           \
            int row = wm * 32 + f * 16 + a_r;                                     \
            LDMX4(ah[f], smaddr(&sA[s][row * SASTRIDE + kk + a_k8]));             \
        }                                                                         \
        unsigned bh[2][4], bl[2][4];                                              \
        _Pragma("unroll") for (int nb = 0; nb < 2; nb++) {                        \
            int n = wn * 32 + nb * 16 + b_n;                                      \
            LDMX4(bh[nb], smaddr(&sWh[s][n * SASTRIDE + kk + b_k8]));             \
            LDMX4(bl[nb], smaddr(&sWl[s][n * SASTRIDE + kk + b_k8]));             \
        }                                                                         \
        _Pragma("unroll") for (int f = 0; f < 2; f++) {                           \
            _Pragma("unroll") for (int nb = 0; nb < 2; nb++) {                    \
                MMA16816(acc[f][nb * 2],     ah[f], bh[nb][0], bh[nb][1]);        \
                MMA16816(acc[f][nb * 2 + 1], ah[f], bh[nb][2], bh[nb][3]);        \
                MMA16816(acc[f][nb * 2],     ah[f], bl[nb][0], bl[nb][1]);        \
                MMA16816(acc[f][nb * 2 + 1], ah[f], bl[nb][2], bl[nb][3]);        \
            }                                                                     \
        }                                                                         \
    }

// -------- embed GEMM: h = fp16(x) @ (Wh+Wl) + b -----------------------------
__global__ void __launch_bounds__(256, 2) gemm_embed(const float* __restrict__ xin,
                                                     const float* __restrict__ bias,
                                                     int nrows) {
    __shared__ __align__(16) __half sA[2][128 * SASTRIDE];
    __shared__ __align__(16) __half sWh[2][64 * SASTRIDE];
    __shared__ __align__(16) __half sWl[2][64 * SASTRIDE];

    const int colBase = blockIdx.x * 64;
    const __half* Wt_h = g_Wth + (size_t)colBase * HH;
    const __half* Wt_l = g_Wtl + (size_t)colBase * HH;

    const int tid = threadIdx.x;
    const int wid = tid >> 5, lane = tid & 31;
    const int wm = wid >> 1, wn = wid & 1;
    const int rowBase = blockIdx.y * 128;

    const int s_r = tid >> 2;
    const int s_kq = (tid & 3) * 8;
    const int gr0 = rowBase + s_r;
    const int gr1 = gr0 + 64;

    float acc[2][4][4];
#pragma unroll
    for (int f = 0; f < 2; f++)
#pragma unroll
        for (int nf = 0; nf < 4; nf++)
#pragma unroll
            for (int q = 0; q < 4; q++) acc[f][nf][q] = 0.0f;

    const int a_r = (lane & 7) + ((lane >> 3) & 1) * 8;
    const int a_k8 = ((lane >> 4) & 1) * 8;
    const int b_n = (lane & 7) + ((lane >> 4) & 1) * 8;
    const int b_k8 = ((lane >> 3) & 1) * 8;

    uint4 ra0, ra1, rwh, rwl;

#define CVT8(dst, gp)                                                             \
    do {                                                                          \
        float4 xa = *(const float4*)(gp);                                        \
        float4 xb = *(const float4*)((gp) + 4);                                  \
        __half2 p0 = __floats2half2_rn(xa.x, xa.y);                              \
        __half2 p1 = __floats2half2_rn(xa.z, xa.w);                              \
        __half2 p2 = __floats2half2_rn(xb.x, xb.y);                              \
        __half2 p3 = __floats2half2_rn(xb.z, xb.w);                              \
        dst = make_uint4(*(unsigned*)&p0, *(unsigned*)&p1,                        \
                         *(unsigned*)&p2, *(unsigned*)&p3);                       \
    } while (0)

#define E_LOAD(kc)                                                                \
    do {                                                                          \
        int k0_ = (kc) * 32;                                                      \
        if (gr0 < nrows) CVT8(ra0, xin + (size_t)gr0 * HH + k0_ + s_kq);          \
        else ra0 = make_uint4(0, 0, 0, 0);                                        \
        if (gr1 < nrows) CVT8(ra1, xin + (size_t)gr1 * HH + k0_ + s_kq);          \
        else ra1 = make_uint4(0, 0, 0, 0);                                        \
        rwh = *(const uint4*)(Wt_h + (size_t)s_r * HH + k0_ + s_kq);              \
        rwl = *(const uint4*)(Wt_l + (size_t)s_r * HH + k0_ + s_kq);              \
    } while (0)

#define E_STORE(s)                                                                \
    do {                                                                          \
        *(uint4*)&sA[s][s_r * SASTRIDE + s_kq] = ra0;                             \
        *(uint4*)&sA[s][(s_r + 64) * SASTRIDE + s_kq] = ra1;                      \
        *(uint4*)&sWh[s][s_r * SASTRIDE + s_kq] = rwh;                            \
        *(uint4*)&sWl[s][s_r * SASTRIDE + s_kq] = rwl;                            \
    } while (0)

    E_LOAD(0);
    E_STORE(0);
    __syncthreads();
#pragma unroll
    for (int kc = 0; kc < 4; kc++) {
        if (kc < 3) E_LOAD(kc + 1);
        const int s = kc & 1;
        GEMM_COMPUTE(s)
        if (kc < 3) {
            __syncthreads();
            E_STORE((kc + 1) & 1);
            __syncthreads();
        }
    }
#undef E_LOAD
#undef E_STORE
#undef CVT8

    const int gid = lane >> 2, qid = lane & 3;
#pragma unroll
    for (int f = 0; f < 2; f++) {
        int rbase = rowBase + wm * 32 + f * 16 + gid;
#pragma unroll
        for (int nf = 0; nf < 4; nf++) {
            int col = colBase + wn * 32 + nf * 8 + qid * 2;
            float bx = bias[col], by = bias[col + 1];
#pragma unroll
            for (int half_ = 0; half_ < 2; half_++) {
                int row = rbase + half_ * 8;
                if (row >= nrows) continue;
                *(__half2*)(g_hh + (size_t)row * HH + col) =
                    __floats2half2_rn(acc[f][nf][half_ * 2] + bx,
                                      acc[f][nf][half_ * 2 + 1] + by);
            }
        }
    }
}

// -------- layer GEMM into ping-pong buffer, row-range restricted -----------
__global__ void __launch_bounds__(256, 3) gemm_layer(int mat0, int bufsel,
                                                     int rowOff, int nrows) {
    __shared__ __align__(16) __half sA[2][128 * SASTRIDE];
    __shared__ __align__(16) __half sWh[2][64 * SASTRIDE];
    __shared__ __align__(16) __half sWl[2][64 * SASTRIDE];

    const int matSel = blockIdx.x >> 1;
    const int colBase = (blockIdx.x & 1) * 64;
    const int mat = mat0 + matSel;
    const __half* Wt_h = g_Wth + (size_t)mat * HH * HH + (size_t)colBase * HH;
    const __half* Wt_l = g_Wtl + (size_t)mat * HH * HH + (size_t)colBase * HH;

    const int tid = threadIdx.x;
    const int wid = tid >> 5, lane = tid & 31;
    const int wm = wid >> 1, wn = wid & 1;
    const int rowBase = rowOff + blockIdx.y * 128;

    const int s_r = tid >> 2;
    const int s_kq = (tid & 3) * 8;
    const int gr0 = rowBase + s_r;
    const int gr1 = gr0 + 64;
    const unsigned sz0 = (gr0 < nrows) ? 16u : 0u;
    const unsigned sz1 = (gr1 < nrows) ? 16u : 0u;

    float acc[2][4][4];
#pragma unroll
    for (int f = 0; f < 2; f++)
#pragma unroll
        for (int nf = 0; nf < 4; nf++)
#pragma unroll
            for (int q = 0; q < 4; q++) acc[f][nf][q] = 0.0f;

    const int a_r = (lane & 7) + ((lane >> 3) & 1) * 8;
    const int a_k8 = ((lane >> 4) & 1) * 8;
    const int b_n = (lane & 7) + ((lane >> 4) & 1) * 8;
    const int b_k8 = ((lane >> 3) & 1) * 8;

#define L_ISSUE(kc, s)                                                             \
    do {                                                                           \
        int k0_ = (kc) * 32;                                                       \
        CPA16(smaddr(&sA[s][s_r * SASTRIDE + s_kq]),                               \
              g_hh + (size_t)gr0 * HH + k0_ + s_kq, sz0);                          \
        CPA16(smaddr(&sA[s][(s_r + 64) * SASTRIDE + s_kq]),                        \
              g_hh + (size_t)gr1 * HH + k0_ + s_kq, sz1);                          \
        CPA16(smaddr(&sWh[s][s_r * SASTRIDE + s_kq]),                              \
              Wt_h + (size_t)s_r * HH + k0_ + s_kq, 16u);                          \
        CPA16(smaddr(&sWl[s][s_r * SASTRIDE + s_kq]),                              \
              Wt_l + (size_t)s_r * HH + k0_ + s_kq, 16u);                          \
        asm volatile("cp.async.commit_group;" ::: "memory");                       \
    } while (0)

    L_ISSUE(0, 0);
#pragma unroll
    for (int kc = 0; kc < 4; kc++) {
        if (kc < 3) L_ISSUE(kc + 1, (kc + 1) & 1);
        if (kc < 3)
            asm volatile("cp.async.wait_group 1;" ::: "memory");
        else
            asm volatile("cp.async.wait_group 0;" ::: "memory");
        __syncthreads();
        const int s = kc & 1;
        GEMM_COMPUTE(s)
        if (kc < 3) __syncthreads();
    }
#undef L_ISSUE

    const int gid = lane >> 2, qid = lane & 3;
    __half* outh = matSel ? g_Bbuf[bufsel] : g_Abuf[bufsel];
#pragma unroll
    for (int f = 0; f < 2; f++) {
        int rbase = rowBase + wm * 32 + f * 16 + gid;
#pragma unroll
        for (int nf = 0; nf < 4; nf++) {
            int col = colBase + wn * 32 + nf * 8 + qid * 2;
#pragma unroll
            for (int half_ = 0; half_ < 2; half_++) {
                int row = rbase + half_ * 8;
                if (row >= nrows) continue;
                *(__half2*)(outh + (size_t)row * HH + col) =
                    __floats2half2_rn(acc[f][nf][half_ * 2], acc[f][nf][half_ * 2 + 1]);
            }
        }
    }
}

// -------- gather core (reads ping-pong buffers) ------------------------------
__device__ __forceinline__ float4 gather_node(const __half* __restrict__ Ah,
                                              const __half* __restrict__ Bh,
                                              const float* __restrict__ bm,
                                              int t, int lane) {
    int d = g_deg[t];
    int o = g_off[t];
    size_t base = (size_t)t * HH + lane * 4;

    float4 bmv = *(const float4*)(bm + lane * 4);
    uint2 bvp = *(const uint2*)(Bh + base);
    float2 bq0 = __half22float2(*(__half2*)&bvp.x);
    float2 bq1 = __half22float2(*(__half2*)&bvp.y);
    float dd = (float)d;
    float4 acc;
    acc.x = dd * (bq0.x + bmv.x);
    acc.y = dd * (bq0.y + bmv.y);
    acc.z = dd * (bq1.x + bmv.z);
    acc.w = dd * (bq1.y + bmv.w);

    int i = 0;
    for (; i + 4 <= d; i += 4) {
        int s0 = g_col[o + i];
        int s1 = g_col[o + i + 1];
        int s2 = g_col[o + i + 2];
        int s3 = g_col[o + i + 3];
        uint2 v0 = *(const uint2*)(Ah + (size_t)s0 * HH + lane * 4);
        uint2 v1 = *(const uint2*)(Ah + (size_t)s1 * HH + lane * 4);
        uint2 v2 = *(const uint2*)(Ah + (size_t)s2 * HH + lane * 4);
        uint2 v3 = *(const uint2*)(Ah + (size_t)s3 * HH + lane * 4);
        float2 a0 = __half22float2(*(__half2*)&v0.x), a1 = __half22float2(*(__half2*)&v0.y);
        float2 b0 = __half22float2(*(__half2*)&v1.x), b1 = __half22float2(*(__half2*)&v1.y);
        float2 c0 = __half22float2(*(__half2*)&v2.x), c1 = __half22float2(*(__half2*)&v2.y);
        float2 d0 = __half22float2(*(__half2*)&v3.x), d1 = __half22float2(*(__half2*)&v3.y);
        acc.x += (a0.x + b0.x) + (c0.x + d0.x);
        acc.y += (a0.y + b0.y) + (c0.y + d0.y);
        acc.z += (a1.x + b1.x) + (c1.x + d1.x);
        acc.w += (a1.y + b1.y) + (c1.y + d1.y);
    }
    for (; i < d; i++) {
        int s0 = g_col[o + i];
        uint2 v0 = *(const uint2*)(Ah + (size_t)s0 * HH + lane * 4);
        float2 a0 = __half22float2(*(__half2*)&v0.x);
        float2 a1 = __half22float2(*(__half2*)&v0.y);
        acc.x += a0.x;
        acc.y += a0.y;
        acc.z += a1.x;
        acc.w += a1.y;
    }

    uint2 hh2 = *(const uint2*)(g_hh + base);
    float2 h0 = __half22float2(*(__half2*)&hh2.x);
    float2 h1 = __half22float2(*(__half2*)&hh2.y);
    float4 v;
    v.x = fmaxf(h0.x + acc.x, 0.0f);
    v.y = fmaxf(h0.y + acc.y, 0.0f);
    v.z = fmaxf(h1.x + acc.z, 0.0f);
    v.w = fmaxf(h1.y + acc.w, 0.0f);
    return v;
}

// mid-layer gather: write new h (fp16), row-range restricted
__global__ void __launch_bounds__(256) gather_relu(const float* __restrict__ bm,
                                                   int bufsel, int rowOff, int nrows) {
    int t = rowOff + blockIdx.x * 8 + threadIdx.y;
    if (t >= nrows) return;
    int lane = threadIdx.x;
    float4 v = gather_node(g_Abuf[bufsel], g_Bbuf[bufsel], bm, t, lane);
    __half2 o0 = __floats2half2_rn(v.x, v.y);
    __half2 o1 = __floats2half2_rn(v.z, v.w);
    uint2 ph;
    ph.x = *(unsigned*)&o0;
    ph.y = *(unsigned*)&o1;
    *(uint2*)(g_hh + (size_t)t * HH + lane * 4) = ph;
}

// last layer: fused mean-pool accumulation
__global__ void __launch_bounds__(256) gather_pool(const float* __restrict__ bm,
                                                   int bufsel, int nrows) {
    __shared__ float4 sv[8][32];
    __shared__ int sb[8];
    int t = blockIdx.x * 8 + threadIdx.y;
    int lane = threadIdx.x;

    float4 v = make_float4(0.f, 0.f, 0.f, 0.f);
    int bat = -1;
    if (t < nrows) {
        v = gather_node(g_Abuf[bufsel], g_Bbuf[bufsel], bm, t, lane);
        bat = g_batchi[t];
    }
    sv[threadIdx.y][lane] = v;
    if (lane == 0) sb[threadIdx.y] = bat;
    __syncthreads();

    if (threadIdx.y == 0) {
        float4 acc = make_float4(0.f, 0.f, 0.f, 0.f);
        int cur = -1;
#pragma unroll
        for (int j = 0; j < 8; j++) {
            int b = sb[j];
            if (b < 0) continue;
            if (b != cur) {
                if (cur >= 0) {
                    float* gp = g_gsum + cur * HH + lane * 4;
                    atomicAdd(gp + 0, acc.x);
                    atomicAdd(gp + 1, acc.y);
                    atomicAdd(gp + 2, acc.z);
                    atomicAdd(gp + 3, acc.w);
                }
                acc = make_float4(0.f, 0.f, 0.f, 0.f);
                cur = b;
            }
            float4 w = sv[j][lane];
            acc.x += w.x;
            acc.y += w.y;
            acc.z += w.z;
            acc.w += w.w;
        }
        if (cur >= 0) {
            float* gp = g_gsum + cur * HH + lane * 4;
            atomicAdd(gp + 0, acc.x);
            atomicAdd(gp + 1, acc.y);
            atomicAdd(gp + 2, acc.z);
            atomicAdd(gp + 3, acc.w);
        }
    }
}

// -------- readout --------
__global__ void r1_kernel(const float* __restrict__ W1, const float* __restrict__ b1) {
    int idx = blockIdx.x * blockDim.x + threadIdx.x;
    if (idx >= BB * 2 * HH) return;
    int b = idx >> 8;
    int j = idx & 255;
    int cnt = g_cnt[b];
    float inv = 1.0f / (float)(cnt > 0 ? cnt : 1);
    float s = 0.0f;
#pragma unroll 8
    for (int k = 0; k < HH; k++) s = fmaf(g_gsum[b * HH + k], W1[(size_t)k * 256 + j], s);
    s = s * inv + b1[j];
    g_t1[idx] = s > 0.0f ? s : 0.0f;
}

__global__ void r2_kernel(const float* __restrict__ W2, const float* __restrict__ b2,
                          float* __restrict__ out) {
    int idx = blockIdx.x * blockDim.x + threadIdx.x;
    if (idx >= BB * MM) return;
    int b = idx >> 11;
    int m = idx & 2047;
    float s = b2[m];
#pragma unroll 8
    for (int k = 0; k < 2 * HH; k++)
        s = fmaf(g_t1[b * 2 * HH + k], W2[(size_t)k * MM + m], s);
    float sig = 1.0f / (1.0f + expf(-s));
    out[idx] = sig * 6.283185307179586f;
}

// ----------------------------------------------------------------
extern "C" void kernel_launch(void* const* d_in, const int* in_sizes, int n_in,
                              void* d_out, int out_size) {
    const float* x       = (const float*)d_in[0];
    const void*  eidx    = d_in[1];
    const void*  batchp  = d_in[2];
    const float* W_embed = (const float*)d_in[3];
    const float* b_embed = (const float*)d_in[4];
    const float* Wm      = (const float*)d_in[5];
    const float* bm      = (const float*)d_in[6];
    const float* W1      = (const float*)d_in[7];
    const float* b1      = (const float*)d_in[8];
    const float* W2      = (const float*)d_in[9];
    const float* b2      = (const float*)d_in[10];
    float* out = (float*)d_out;

    int nrows = in_sizes[0] / HH;
    if (nrows > NN) nrows = NN;

    // lazily created side stream + events (host objects only; identical work
    // enqueued every call)
    static cudaStream_t s2 = nullptr;
    static cudaEvent_t evFork = nullptr, evJoin = nullptr;
    static cudaEvent_t eG[4] = {nullptr, nullptr, nullptr, nullptr};
    static cudaEvent_t eM[2] = {nullptr, nullptr};
    if (s2 == nullptr) {
        cudaStreamCreateWithFlags(&s2, cudaStreamNonBlocking);
        cudaEventCreateWithFlags(&evFork, cudaEventDisableTiming);
        cudaEventCreateWithFlags(&evJoin, cudaEventDisableTiming);
        for (int i = 0; i < 4; i++) cudaEventCreateWithFlags(&eG[i], cudaEventDisableTiming);
        for (int i = 0; i < 2; i++) cudaEventCreateWithFlags(&eM[i], cudaEventDisableTiming);
    }

    const int nb_scan = (NN + 1023) / 1024;
    const int eg2 = (EE / 2 + 255) / 256;
    const int gx = (nrows + 127) / 128;

    // row halves (half0 multiple of 128)
    const int half0 = ((nrows / 2 + 127) / 128) * 128;
    const int gy0 = half0 / 128;
    const int rem = nrows - half0;
    const int gy1 = (rem + 127) / 128;
    const int gb0 = half0 / 8;                 // gather blocks half0 (8 nodes/blk)
    const int gb1 = (rem + 7) / 8;

    // prologue
    zero_kernel<<<(NN + 255) / 256, 256>>>();
    detect_kernel<<<1, 256>>>(eidx, batchp);

    // fork: CSR build on s2 (small-grid convert leaves SM room for GEMMs)
    cudaEventRecord(evFork, 0);
    cudaStreamWaitEvent(s2, evFork, 0);
    convert_kernel<<<296, 256, 0, s2>>>(eidx, batchp);
    scan1_kernel<<<nb_scan, 1024, 0, s2>>>();
    scan2_kernel<<<1, 128, 0, s2>>>(nb_scan);
    scan3_kernel<<<nb_scan, 1024, 0, s2>>>();
    fill_kernel<<<eg2, 256, 0, s2>>>();
    cudaEventRecord(evJoin, s2);

    // main: weights + embed + layer-0 GEMM (buf 0), concurrent with CSR
    prep_kernel<<<(7 * HH * HH + 255) / 256, 256>>>(W_embed, Wm);
    gemm_embed<<<dim3(2, gx), 256>>>(x, b_embed, nrows);
    gemm_layer<<<dim3(4, gx), 256>>>(1, 0, 0, nrows);

    cudaStreamWaitEvent(0, evJoin, 0);

    // ---- layer 0 gather (buf0) pipelined with layer-1 GEMM (buf1) ----
    gather_relu<<<gb0, dim3(32, 8)>>>(bm, 0, 0, nrows);
    cudaEventRecord(eG[0], 0);
    gather_relu<<<gb1, dim3(32, 8)>>>(bm, 0, half0, nrows);
    cudaEventRecord(eG[1], 0);

    cudaStreamWaitEvent(s2, eG[0], 0);
    gemm_layer<<<dim3(4, gy0), 256, 0, s2>>>(3, 1, 0, nrows);
    cudaStreamWaitEvent(s2, eG[1], 0);
    gemm_layer<<<dim3(4, gy1), 256, 0, s2>>>(3, 1, half0, nrows);
    cudaEventRecord(eM[0], s2);

    // ---- layer 1 gather (buf1) pipelined with layer-2 GEMM (buf0) ----
    cudaStreamWaitEvent(0, eM[0], 0);
    gather_relu<<<gb0, dim3(32, 8)>>>(bm + HH, 1, 0, nrows);
    cudaEventRecord(eG[2], 0);
    gather_relu<<<gb1, dim3(32, 8)>>>(bm + HH, 1, half0, nrows);
    cudaEventRecord(eG[3], 0);

    cudaStreamWaitEvent(s2, eG[2], 0);
    gemm_layer<<<dim3(4, gy0), 256, 0, s2>>>(5, 0, 0, nrows);
    cudaStreamWaitEvent(s2, eG[3], 0);
    gemm_layer<<<dim3(4, gy1), 256, 0, s2>>>(5, 0, half0, nrows);
    cudaEventRecord(eM[1], s2);

    // ---- layer 2 gather fused with pooling (buf0) ----
    cudaStreamWaitEvent(0, eM[1], 0);
    gather_pool<<<(nrows + 7) / 8, dim3(32, 8)>>>(bm + 2 * HH, 0, nrows);

    r1_kernel<<<(BB * 2 * HH + 255) / 256, 256>>>(W1, b1);
    r2_kernel<<<(BB * MM + 255) / 256, 256>>>(W2, b2, out);
}

// round 15
// speedup vs baseline: 1.0800x; 1.0800x over previous
#include <cuda_runtime.h>
#include <cuda_fp16.h>
#include <math.h>

// Problem constants (fixed shapes)
#define NN 100000
#define EE 1600000
#define HH 128
#define BB 16
#define MM 2048
#define LL 3

// -------- static device scratch (no allocations allowed) --------
__device__ __half g_Ah[(size_t)NN * HH];   // h @ Wm_top (fp16)
__device__ __half g_Bh[(size_t)NN * HH];   // h @ Wm_bot (fp16)
__device__ __half g_hh[(size_t)NN * HH];   // node hidden state (fp16)
__device__ __half g_Wth[7 * HH * HH];      // W^T hi (fp16)
__device__ __half g_Wtl[7 * HH * HH];      // W^T lo (fp16 of residual)
__device__ int    g_src[EE];
__device__ int    g_tgt[EE];
__device__ int    g_rank[EE];
__device__ int    g_col[EE];
__device__ int    g_deg[NN];
__device__ int    g_off[NN];
__device__ int    g_batchi[NN];
__device__ int    g_bsums[128];
__device__ float  g_gsum[BB * HH];
__device__ int    g_cnt[BB];
__device__ float  g_t1[BB * 2 * HH];
__device__ int    g_flags;

// ----------------------------------------------------------------
__global__ void zero_kernel() {
    int i = blockIdx.x * blockDim.x + threadIdx.x;
    if (i < NN) g_deg[i] = 0;
    if (i < BB * HH) g_gsum[i] = 0.0f;
    if (i < BB) g_cnt[i] = 0;
    if (i == 0) g_flags = 0;
}

__global__ void detect_kernel(const void* __restrict__ ep, const void* __restrict__ bp) {
    int j = threadIdx.x;
    long long pos = (long long)j * (EE / 256);
    long long v = ((const long long*)ep)[pos];
    if (v < 0 || v >= NN) atomicOr(&g_flags, 1);
    long long bpos = (long long)(NN / 4) + j;
    long long bv = ((const long long*)bp)[bpos];
    if (bv < 0 || bv >= BB) atomicOr(&g_flags, 2);
}

// weight transpose + fp16 hi/lo split
__global__ void prep_kernel(const float* __restrict__ We, const float* __restrict__ Wm) {
    int idx = blockIdx.x * blockDim.x + threadIdx.x;
    if (idx >= 7 * HH * HH) return;
    int mat = idx >> 14;
    int r = (idx >> 7) & 127;
    int c = idx & 127;
    float v;
    if (mat == 0) {
        v = We[r * HH + c];
    } else {
        int l = (mat - 1) >> 1;
        int hf = (mat - 1) & 1;
        v = Wm[((size_t)l * 2 * HH + hf * HH + r) * HH + c];
    }
    __half hi = __float2half_rn(v);
    g_Wth[mat * HH * HH + c * HH + r] = hi;
    g_Wtl[mat * HH * HH + c * HH + r] = __float2half_rn(v - __half2float(hi));
}

// convert + degree histogram with ranks + batch counts (small grid-stride)
__global__ void __launch_bounds__(256) convert_kernel(const void* __restrict__ ep,
                                                      const void* __restrict__ bp) {
    int f = g_flags;
    int stride = gridDim.x * blockDim.x;
    for (int i = blockIdx.x * blockDim.x + threadIdx.x; i < EE / 2; i += stride) {
        int s0, s1, t0, t1;
        if (f & 1) {
            int2 sv = ((const int2*)ep)[i];
            int2 tv = ((const int2*)((const int*)ep + EE))[i];
            s0 = sv.x; s1 = sv.y; t0 = tv.x; t1 = tv.y;
        } else {
            longlong2 sv = ((const longlong2*)ep)[i];
            longlong2 tv = ((const longlong2*)((const long long*)ep + EE))[i];
            s0 = (int)sv.x; s1 = (int)sv.y; t0 = (int)tv.x; t1 = (int)tv.y;
        }
        *(int2*)(g_src + 2 * i) = make_int2(s0, s1);
        *(int2*)(g_tgt + 2 * i) = make_int2(t0, t1);
        int r0 = atomicAdd(&g_deg[t0], 1);
        int r1 = atomicAdd(&g_deg[t1], 1);
        *(int2*)(g_rank + 2 * i) = make_int2(r0, r1);
    }
    for (int i = blockIdx.x * blockDim.x + threadIdx.x; i < NN; i += stride) {
        int b = (f & 2) ? ((const int*)bp)[i] : (int)((const long long*)bp)[i];
        g_batchi[i] = b;
        atomicAdd(&g_cnt[b], 1);
    }
}

__global__ void scan1_kernel() {
    __shared__ int sh[1024];
    int t = threadIdx.x;
    int i = blockIdx.x * 1024 + t;
    int v = (i < NN) ? g_deg[i] : 0;
    sh[t] = v;
    __syncthreads();
#pragma unroll
    for (int s = 1; s < 1024; s <<= 1) {
        int x = (t >= s) ? sh[t - s] : 0;
        __syncthreads();
        sh[t] += x;
        __syncthreads();
    }
    if (i < NN) g_off[i] = sh[t] - v;
    if (t == 1023) g_bsums[blockIdx.x] = sh[1023];
}

__global__ void scan2_kernel(int nb) {
    __shared__ int sh[128];
    int t = threadIdx.x;
    int v = (t < nb) ? g_bsums[t] : 0;
    sh[t] = v;
    __syncthreads();
#pragma unroll
    for (int s = 1; s < 128; s <<= 1) {
        int x = (t >= s) ? sh[t - s] : 0;
        __syncthreads();
        sh[t] += x;
        __syncthreads();
    }
    if (t < nb) g_bsums[t] = sh[t] - v;
}

__global__ void scan3_kernel() {
    int i = blockIdx.x * 1024 + threadIdx.x;
    if (i < NN) g_off[i] += g_bsums[blockIdx.x];
}

__global__ void fill_kernel() {
    int i = blockIdx.x * blockDim.x + threadIdx.x;
    if (i >= EE / 2) return;
    int2 t = *(const int2*)(g_tgt + 2 * i);
    int2 s = *(const int2*)(g_src + 2 * i);
    int2 r = *(const int2*)(g_rank + 2 * i);
    g_col[g_off[t.x] + r.x] = s.x;
    g_col[g_off[t.y] + r.y] = s.y;
}

// -------- shared GEMM helpers ----------------------------------------------
#define SASTRIDE 40

__device__ __forceinline__ unsigned smaddr(const void* p) {
    return (unsigned)__cvta_generic_to_shared(p);
}

#define LDMX4(R, addr)                                                           \
    asm volatile("ldmatrix.sync.aligned.m8n8.x4.shared.b16 {%0,%1,%2,%3}, [%4];" \
                 : "=r"((R)[0]), "=r"((R)[1]), "=r"((R)[2]), "=r"((R)[3])        \
                 : "r"(addr))

#define MMA16816(C, A, b0, b1)                                                   \
    asm volatile(                                                                \
        "mma.sync.aligned.m16n8k16.row.col.f32.f16.f16.f32 "                     \
        "{%0,%1,%2,%3}, {%4,%5,%6,%7}, {%8,%9}, {%0,%1,%2,%3};"                  \
        : "+f"((C)[0]), "+f"((C)[1]), "+f"((C)[2]), "+f"((C)[3])                 \
        : "r"((A)[0]), "r"((A)[1]), "r"((A)[2]), "r"((A)[3]), "r"(b0), "r"(b1))

#define CPA16(dst, src, sz)                                                       \
    asm volatile("cp.async.cg.shared.global [%0], [%1], 16, %2;"                  \
                 :: "r"(dst), "l"(src), "r"(sz))

#define GEMM_COMPUTE(s)                                                           \
    _Pragma("unroll") for (int ks = 0; ks < 2; ks++) {                            \
        const int kk = ks * 16;                                                   \
        unsigned ah[2][4];                                                        \
        _Pragma("unroll") for (int f = 0; f < 2; f++) {                           \
            int row = wm * 32 + f * 16 + a_r;                                     \
            LDMX4(ah[f], smaddr(&sA[s][row * SASTRIDE + kk + a_k8]));             \
        }                                                                         \
        unsigned bh[2][4], bl[2][4];                                              \
        _Pragma("unroll") for (int nb = 0; nb < 2; nb++) {                        \
            int n = wn * 32 + nb * 16 + b_n;                                      \
            LDMX4(bh[nb], smaddr(&sWh[s][n * SASTRIDE + kk + b_k8]));             \
            LDMX4(bl[nb], smaddr(&sWl[s][n * SASTRIDE + kk + b_k8]));             \
        }                                                                         \
        _Pragma("unroll") for (int f = 0; f < 2; f++) {                           \
            _Pragma("unroll") for (int nb = 0; nb < 2; nb++) {                    \
                MMA16816(acc[f][nb * 2],     ah[f], bh[nb][0], bh[nb][1]);        \
                MMA16816(acc[f][nb * 2 + 1], ah[f], bh[nb][2], bh[nb][3]);        \
                MMA16816(acc[f][nb * 2],     ah[f], bl[nb][0], bl[nb][1]);        \
                MMA16816(acc[f][nb * 2 + 1], ah[f], bl[nb][2], bl[nb][3]);        \
            }                                                                     \
        }                                                                         \
    }

// -------- embed GEMM: h = fp16(x) @ (Wh+Wl) + b -----------------------------
__global__ void __launch_bounds__(256, 2) gemm_embed(const float* __restrict__ xin,
                                                     const float* __restrict__ bias,
                                                     int nrows) {
    __shared__ __align__(16) __half sA[2][128 * SASTRIDE];
    __shared__ __align__(16) __half sWh[2][64 * SASTRIDE];
    __shared__ __align__(16) __half sWl[2][64 * SASTRIDE];

    const int colBase = blockIdx.x * 64;
    const __half* Wt_h = g_Wth + (size_t)colBase * HH;
    const __half* Wt_l = g_Wtl + (size_t)colBase * HH;

    const int tid = threadIdx.x;
    const int wid = tid >> 5, lane = tid & 31;
    const int wm = wid >> 1, wn = wid & 1;
    const int rowBase = blockIdx.y * 128;

    const int s_r = tid >> 2;
    const int s_kq = (tid & 3) * 8;
    const int gr0 = rowBase + s_r;
    const int gr1 = gr0 + 64;

    float acc[2][4][4];
#pragma unroll
    for (int f = 0; f < 2; f++)
#pragma unroll
        for (int nf = 0; nf < 4; nf++)
#pragma unroll
            for (int q = 0; q < 4; q++) acc[f][nf][q] = 0.0f;

    const int a_r = (lane & 7) + ((lane >> 3) & 1) * 8;
    const int a_k8 = ((lane >> 4) & 1) * 8;
    const int b_n = (lane & 7) + ((lane >> 4) & 1) * 8;
    const int b_k8 = ((lane >> 3) & 1) * 8;

    uint4 ra0, ra1, rwh, rwl;

#define CVT8(dst, gp)                                                             \
    do {                                                                          \
        float4 xa = *(const float4*)(gp);                                        \
        float4 xb = *(const float4*)((gp) + 4);                                  \
        __half2 p0 = __floats2half2_rn(xa.x, xa.y);                              \
        __half2 p1 = __floats2half2_rn(xa.z, xa.w);                              \
        __half2 p2 = __floats2half2_rn(xb.x, xb.y);                              \
        __half2 p3 = __floats2half2_rn(xb.z, xb.w);                              \
        dst = make_uint4(*(unsigned*)&p0, *(unsigned*)&p1,                        \
                         *(unsigned*)&p2, *(unsigned*)&p3);                       \
    } while (0)

#define E_LOAD(kc)                                                                \
    do {                                                                          \
        int k0_ = (kc) * 32;                                                      \
        if (gr0 < nrows) CVT8(ra0, xin + (size_t)gr0 * HH + k0_ + s_kq);          \
        else ra0 = make_uint4(0, 0, 0, 0);                                        \
        if (gr1 < nrows) CVT8(ra1, xin + (size_t)gr1 * HH + k0_ + s_kq);          \
        else ra1 = make_uint4(0, 0, 0, 0);                                        \
        rwh = *(const uint4*)(Wt_h + (size_t)s_r * HH + k0_ + s_kq);              \
        rwl = *(const uint4*)(Wt_l + (size_t)s_r * HH + k0_ + s_kq);              \
    } while (0)

#define E_STORE(s)                                                                \
    do {                                                                          \
        *(uint4*)&sA[s][s_r * SASTRIDE + s_kq] = ra0;                             \
        *(uint4*)&sA[s][(s_r + 64) * SASTRIDE + s_kq] = ra1;                      \
        *(uint4*)&sWh[s][s_r * SASTRIDE + s_kq] = rwh;                            \
        *(uint4*)&sWl[s][s_r * SASTRIDE + s_kq] = rwl;                            \
    } while (0)

    E_LOAD(0);
    E_STORE(0);
    __syncthreads();
#pragma unroll
    for (int kc = 0; kc < 4; kc++) {
        if (kc < 3) E_LOAD(kc + 1);
        const int s = kc & 1;
        GEMM_COMPUTE(s)
        if (kc < 3) {
            __syncthreads();
            E_STORE((kc + 1) & 1);
            __syncthreads();
        }
    }
#undef E_LOAD
#undef E_STORE
#undef CVT8

    const int gid = lane >> 2, qid = lane & 3;
#pragma unroll
    for (int f = 0; f < 2; f++) {
        int rbase = rowBase + wm * 32 + f * 16 + gid;
#pragma unroll
        for (int nf = 0; nf < 4; nf++) {
            int col = colBase + wn * 32 + nf * 8 + qid * 2;
            float bx = bias[col], by = bias[col + 1];
#pragma unroll
            for (int half_ = 0; half_ < 2; half_++) {
                int row = rbase + half_ * 8;
                if (row >= nrows) continue;
                *(__half2*)(g_hh + (size_t)row * HH + col) =
                    __floats2half2_rn(acc[f][nf][half_ * 2] + bx,
                                      acc[f][nf][half_ * 2 + 1] + by);
            }
        }
    }
}

// -------- layer GEMM: A/B = hh @ (Wh+Wl), cp.async double-buffered ----------
__global__ void __launch_bounds__(256, 3) gemm_layer(int mat0, int nrows) {
    __shared__ __align__(16) __half sA[2][128 * SASTRIDE];
    __shared__ __align__(16) __half sWh[2][64 * SASTRIDE];
    __shared__ __align__(16) __half sWl[2][64 * SASTRIDE];

    const int matSel = blockIdx.x >> 1;
    const int colBase = (blockIdx.x & 1) * 64;
    const int mat = mat0 + matSel;
    const __half* Wt_h = g_Wth + (size_t)mat * HH * HH + (size_t)colBase * HH;
    const __half* Wt_l = g_Wtl + (size_t)mat * HH * HH + (size_t)colBase * HH;

    const int tid = threadIdx.x;
    const int wid = tid >> 5, lane = tid & 31;
    const int wm = wid >> 1, wn = wid & 1;
    const int rowBase = blockIdx.y * 128;

    const int s_r = tid >> 2;
    const int s_kq = (tid & 3) * 8;
    const int gr0 = rowBase + s_r;
    const int gr1 = gr0 + 64;
    const unsigned sz0 = (gr0 < nrows) ? 16u : 0u;
    const unsigned sz1 = (gr1 < nrows) ? 16u : 0u;

    float acc[2][4][4];
#pragma unroll
    for (int f = 0; f < 2; f++)
#pragma unroll
        for (int nf = 0; nf < 4; nf++)
#pragma unroll
            for (int q = 0; q < 4; q++) acc[f][nf][q] = 0.0f;

    const int a_r = (lane & 7) + ((lane >> 3) & 1) * 8;
    const int a_k8 = ((lane >> 4) & 1) * 8;
    const int b_n = (lane & 7) + ((lane >> 4) & 1) * 8;
    const int b_k8 = ((lane >> 3) & 1) * 8;

#define L_ISSUE(kc, s)                                                             \
    do {                                                                           \
        int k0_ = (kc) * 32;                                                       \
        CPA16(smaddr(&sA[s][s_r * SASTRIDE + s_kq]),                               \
              g_hh + (size_t)gr0 * HH + k0_ + s_kq, sz0);                          \
        CPA16(smaddr(&sA[s][(s_r + 64) * SASTRIDE + s_kq]),                        \
              g_hh + (size_t)gr1 * HH + k0_ + s_kq, sz1);                          \
        CPA16(smaddr(&sWh[s][s_r * SASTRIDE + s_kq]),                              \
              Wt_h + (size_t)s_r * HH + k0_ + s_kq, 16u);                          \
        CPA16(smaddr(&sWl[s][s_r * SASTRIDE + s_kq]),                              \
              Wt_l + (size_t)s_r * HH + k0_ + s_kq, 16u);                          \
        asm volatile("cp.async.commit_group;" ::: "memory");                       \
    } while (0)

    L_ISSUE(0, 0);
#pragma unroll
    for (int kc = 0; kc < 4; kc++) {
        if (kc < 3) L_ISSUE(kc + 1, (kc + 1) & 1);
        if (kc < 3)
            asm volatile("cp.async.wait_group 1;" ::: "memory");
        else
            asm volatile("cp.async.wait_group 0;" ::: "memory");
        __syncthreads();
        const int s = kc & 1;
        GEMM_COMPUTE(s)
        if (kc < 3) __syncthreads();
    }
#undef L_ISSUE

    const int gid = lane >> 2, qid = lane & 3;
    __half* outh = matSel ? g_Bh : g_Ah;
#pragma unroll
    for (int f = 0; f < 2; f++) {
        int rbase = rowBase + wm * 32 + f * 16 + gid;
#pragma unroll
        for (int nf = 0; nf < 4; nf++) {
            int col = colBase + wn * 32 + nf * 8 + qid * 2;
#pragma unroll
            for (int half_ = 0; half_ < 2; half_++) {
                int row = rbase + half_ * 8;
                if (row >= nrows) continue;
                *(__half2*)(outh + (size_t)row * HH + col) =
                    __floats2half2_rn(acc[f][nf][half_ * 2], acc[f][nf][half_ * 2 + 1]);
            }
        }
    }
}

// -------- gather core: unroll-8 edge loop for deep MLP ----------------------
__device__ __forceinline__ float4 gather_node(const float* __restrict__ bm,
                                              int t, int lane) {
    int d = __ldg(&g_deg[t]);
    int o = __ldg(&g_off[t]);
    size_t base = (size_t)t * HH + lane * 4;

    float4 bmv = *(const float4*)(bm + lane * 4);
    uint2 bvp = __ldg((const uint2*)(g_Bh + base));
    float2 bq0 = __half22float2(*(__half2*)&bvp.x);
    float2 bq1 = __half22float2(*(__half2*)&bvp.y);
    float dd = (float)d;
    float4 acc;
    acc.x = dd * (bq0.x + bmv.x);
    acc.y = dd * (bq0.y + bmv.y);
    acc.z = dd * (bq1.x + bmv.z);
    acc.w = dd * (bq1.y + bmv.w);

    int i = 0;
    for (; i + 8 <= d; i += 8) {
        int sidx[8];
#pragma unroll
        for (int j = 0; j < 8; j++) sidx[j] = __ldg(&g_col[o + i + j]);
        uint2 vv[8];
#pragma unroll
        for (int j = 0; j < 8; j++)
            vv[j] = __ldg((const uint2*)(g_Ah + (size_t)sidx[j] * HH + lane * 4));
#pragma unroll
        for (int j = 0; j < 8; j++) {
            float2 p0 = __half22float2(*(__half2*)&vv[j].x);
            float2 p1 = __half22float2(*(__half2*)&vv[j].y);
            acc.x += p0.x;
            acc.y += p0.y;
            acc.z += p1.x;
            acc.w += p1.y;
        }
    }
    if (i + 4 <= d) {
        int sidx[4];
#pragma unroll
        for (int j = 0; j < 4; j++) sidx[j] = __ldg(&g_col[o + i + j]);
        uint2 vv[4];
#pragma unroll
        for (int j = 0; j < 4; j++)
            vv[j] = __ldg((const uint2*)(g_Ah + (size_t)sidx[j] * HH + lane * 4));
#pragma unroll
        for (int j = 0; j < 4; j++) {
            float2 p0 = __half22float2(*(__half2*)&vv[j].x);
            float2 p1 = __half22float2(*(__half2*)&vv[j].y);
            acc.x += p0.x;
            acc.y += p0.y;
            acc.z += p1.x;
            acc.w += p1.y;
        }
        i += 4;
    }
    for (; i < d; i++) {
        int s0 = __ldg(&g_col[o + i]);
        uint2 v0 = __ldg((const uint2*)(g_Ah + (size_t)s0 * HH + lane * 4));
        float2 a0 = __half22float2(*(__half2*)&v0.x);
        float2 a1 = __half22float2(*(__half2*)&v0.y);
        acc.x += a0.x;
        acc.y += a0.y;
        acc.z += a1.x;
        acc.w += a1.y;
    }

    uint2 hh2 = __ldg((const uint2*)(g_hh + base));
    float2 h0 = __half22float2(*(__half2*)&hh2.x);
    float2 h1 = __half22float2(*(__half2*)&hh2.y);
    float4 v;
    v.x = fmaxf(h0.x + acc.x, 0.0f);
    v.y = fmaxf(h0.y + acc.y, 0.0f);
    v.z = fmaxf(h1.x + acc.z, 0.0f);
    v.w = fmaxf(h1.y + acc.w, 0.0f);
    return v;
}

// mid-layer: write new h back (fp16)
__global__ void __launch_bounds__(256) gather_relu(const float* __restrict__ bm, int nrows) {
    int t = blockIdx.x * 8 + threadIdx.y;
    if (t >= nrows) return;
    int lane = threadIdx.x;
    float4 v = gather_node(bm, t, lane);
    __half2 o0 = __floats2half2_rn(v.x, v.y);
    __half2 o1 = __floats2half2_rn(v.z, v.w);
    uint2 ph;
    ph.x = *(unsigned*)&o0;
    ph.y = *(unsigned*)&o1;
    *(uint2*)(g_hh + (size_t)t * HH + lane * 4) = ph;
}

// last layer: fuse mean-pool accumulation (no g_hh write, no pool pass)
__global__ void __launch_bounds__(256) gather_pool(const float* __restrict__ bm, int nrows) {
    __shared__ float4 sv[8][32];
    __shared__ int sb[8];
    int t = blockIdx.x * 8 + threadIdx.y;
    int lane = threadIdx.x;

    float4 v = make_float4(0.f, 0.f, 0.f, 0.f);
    int bat = -1;
    if (t < nrows) {
        v = gather_node(bm, t, lane);
        bat = g_batchi[t];
    }
    sv[threadIdx.y][lane] = v;
    if (lane == 0) sb[threadIdx.y] = bat;
    __syncthreads();

    if (threadIdx.y == 0) {
        float4 acc = make_float4(0.f, 0.f, 0.f, 0.f);
        int cur = -1;
#pragma unroll
        for (int j = 0; j < 8; j++) {
            int b = sb[j];
            if (b < 0) continue;
            if (b != cur) {
                if (cur >= 0) {
                    float* gp = g_gsum + cur * HH + lane * 4;
                    atomicAdd(gp + 0, acc.x);
                    atomicAdd(gp + 1, acc.y);
                    atomicAdd(gp + 2, acc.z);
                    atomicAdd(gp + 3, acc.w);
                }
                acc = make_float4(0.f, 0.f, 0.f, 0.f);
                cur = b;
            }
            float4 w = sv[j][lane];
            acc.x += w.x;
            acc.y += w.y;
            acc.z += w.z;
            acc.w += w.w;
        }
        if (cur >= 0) {
            float* gp = g_gsum + cur * HH + lane * 4;
            atomicAdd(gp + 0, acc.x);
            atomicAdd(gp + 1, acc.y);
            atomicAdd(gp + 2, acc.z);
            atomicAdd(gp + 3, acc.w);
        }
    }
}

// -------- readout --------
__global__ void r1_kernel(const float* __restrict__ W1, const float* __restrict__ b1) {
    int idx = blockIdx.x * blockDim.x + threadIdx.x;
    if (idx >= BB * 2 * HH) return;
    int b = idx >> 8;
    int j = idx & 255;
    int cnt = g_cnt[b];
    float inv = 1.0f / (float)(cnt > 0 ? cnt : 1);
    float s = 0.0f;
#pragma unroll 8
    for (int k = 0; k < HH; k++) s = fmaf(g_gsum[b * HH + k], W1[(size_t)k * 256 + j], s);
    s = s * inv + b1[j];
    g_t1[idx] = s > 0.0f ? s : 0.0f;
}

__global__ void r2_kernel(const float* __restrict__ W2, const float* __restrict__ b2,
                          float* __restrict__ out) {
    int idx = blockIdx.x * blockDim.x + threadIdx.x;
    if (idx >= BB * MM) return;
    int b = idx >> 11;
    int m = idx & 2047;
    float s = b2[m];
#pragma unroll 8
    for (int k = 0; k < 2 * HH; k++)
        s = fmaf(g_t1[b * 2 * HH + k], W2[(size_t)k * MM + m], s);
    float sig = 1.0f / (1.0f + expf(-s));
    out[idx] = sig * 6.283185307179586f;
}

// ----------------------------------------------------------------
extern "C" void kernel_launch(void* const* d_in, const int* in_sizes, int n_in,
                              void* d_out, int out_size) {
    const float* x       = (const float*)d_in[0];
    const void*  eidx    = d_in[1];
    const void*  batchp  = d_in[2];
    const float* W_embed = (const float*)d_in[3];
    const float* b_embed = (const float*)d_in[4];
    const float* Wm      = (const float*)d_in[5];
    const float* bm      = (const float*)d_in[6];
    const float* W1      = (const float*)d_in[7];
    const float* b1      = (const float*)d_in[8];
    const float* W2      = (const float*)d_in[9];
    const float* b2      = (const float*)d_in[10];
    float* out = (float*)d_out;

    int nrows = in_sizes[0] / HH;
    if (nrows > NN) nrows = NN;

    static cudaStream_t s2 = nullptr;
    static cudaEvent_t evFork = nullptr, evJoin = nullptr;
    if (s2 == nullptr) {
        cudaStreamCreateWithFlags(&s2, cudaStreamNonBlocking);
        cudaEventCreateWithFlags(&evFork, cudaEventDisableTiming);
        cudaEventCreateWithFlags(&evJoin, cudaEventDisableTiming);
    }

    const int nb_scan = (NN + 1023) / 1024;
    const int eg2 = (EE / 2 + 255) / 256;
    const int gx = (nrows + 127) / 128;

    // prologue (main stream)
    zero_kernel<<<(NN + 255) / 256, 256>>>();
    detect_kernel<<<1, 256>>>(eidx, batchp);

    // fork: CSR build chain on s2, concurrent with prep/embed/layer0 GEMM
    cudaEventRecord(evFork, 0);
    cudaStreamWaitEvent(s2, evFork, 0);

    convert_kernel<<<296, 256, 0, s2>>>(eidx, batchp);
    scan1_kernel<<<nb_scan, 1024, 0, s2>>>();
    scan2_kernel<<<1, 128, 0, s2>>>(nb_scan);
    scan3_kernel<<<nb_scan, 1024, 0, s2>>>();
    fill_kernel<<<eg2, 256, 0, s2>>>();
    cudaEventRecord(evJoin, s2);

    // main stream: weights + embed + first layer GEMM (independent of CSR)
    prep_kernel<<<(7 * HH * HH + 255) / 256, 256>>>(W_embed, Wm);
    gemm_embed<<<dim3(2, gx), 256>>>(x, b_embed, nrows);
    gemm_layer<<<dim3(4, gx), 256>>>(1, nrows);

    // join: gather needs the CSR
    cudaStreamWaitEvent(0, evJoin, 0);

    gather_relu<<<(nrows + 7) / 8, dim3(32, 8)>>>(bm, nrows);
    gemm_layer<<<dim3(4, gx), 256>>>(3, nrows);
    gather_relu<<<(nrows + 7) / 8, dim3(32, 8)>>>(bm + HH, nrows);
    gemm_layer<<<dim3(4, gx), 256>>>(5, nrows);
    gather_pool<<<(nrows + 7) / 8, dim3(32, 8)>>>(bm + 2 * HH, nrows);

    r1_kernel<<<(BB * 2 * HH + 255) / 256, 256>>>(W1, b1);
    r2_kernel<<<(BB * MM + 255) / 256, 256>>>(W2, b2, out);
}